// round 16
// baseline (speedup 1.0000x reference)
#include <cuda_runtime.h>

#define TPB     256
#define NBLOCKS 912      // persistent: ~6 blocks/SM
#define W       512      // column-strip width (= 2 * TPB)
#define H       8        // rows per tile (halves quantization tail vs H=16)

// ---------------------------------------------------------------------------
// out = sum_j x[j] * ( c1[j] + sum_{i<j} x[i] * c2[base(i) + (j-i-1)] )
// c2 = c + n, base(i) = i*(2n-1-i)/2  (row-major packed upper triangle).
//
// R3 tile kernel with two targeted fixes:
//  (1) H=16 -> 8: 8704 tiles on 912 blocks halves the makespan tail.
//  (2) diagonal tiles: 4-row unrolled body with UNGUARDED loads (addresses
//      always in-bounds) and predicated FMAs -> same 8-loads-in-flight MLP
//      as the clean path.
// Reduction: zero kernel + one atomicAdd per block (R3 scheme; the fused
// counter reduction measured slower in R15).
// ---------------------------------------------------------------------------

__global__ void zero_out_kernel(float* out) {
    if (threadIdx.x == 0 && blockIdx.x == 0) out[0] = 0.0f;
}

__device__ __forceinline__ float warp_sum(float v) {
    #pragma unroll
    for (int o = 16; o > 0; o >>= 1) v += __shfl_down_sync(0xffffffffu, v, o);
    return v;
}

__global__ __launch_bounds__(TPB, 6)
void ham_kernel(const float* __restrict__ x,
                const float* __restrict__ c,
                float* __restrict__ out,
                int n) {
    const int t = threadIdx.x;
    const int G = gridDim.x;
    const float* c2 = c + n;

    const int nstrips = n / W;                                    // 16
    const int tps     = W / H;                                    // 64 per (js+1)
    const int ntiles  = (tps / 2) * nstrips * (nstrips + 1);      // 8704

    float sum = 0.0f;

    for (int f = blockIdx.x; f < ntiles; f += G) {
        // strip js: tiles-per-strip = 64*(js+1), prefix(js) = 32*js*(js+1)
        int js = 0;
        while (js + 1 < nstrips && 32 * (js + 1) * (js + 2) <= f) js++;
        const int it = f - 32 * js * (js + 1);

        const int j0  = js * W;
        const int i0  = it * H;
        const int j_a = j0 + t;
        const int j_b = j0 + TPB + t;

        float acc0 = 0.0f, acc1 = 0.0f;
        if (it == 0) {                       // fold degree-1 terms in once
            acc0 = __ldg(c + j_a);
            acc1 = __ldg(c + j_b);
        }

        int iend = i0 + H;
        const int ilim = (js + 1) * W - 1;   // rows valid while i < ilim
        if (iend > ilim) iend = ilim;

        const int base = (i0 * (2 * n - 1 - i0)) >> 1;   // < 2^27, exact
        const float* p = c2 + base + (j_a - i0 - 1);

        if (i0 + H <= j0) {
            // ---- clean path: whole tile strictly above diagonal ----
            #pragma unroll 1
            for (int i = i0; i + 4 <= iend; i += 4) {
                const int o1 = n - 2 - i;
                const int o2 = 2 * n - 5 - 2 * i;
                const int o3 = 3 * n - 9 - 3 * i;
                const float xi0 = __ldg(x + i);
                const float xi1 = __ldg(x + i + 1);
                const float xi2 = __ldg(x + i + 2);
                const float xi3 = __ldg(x + i + 3);
                const float a0 = __ldcs(p);
                const float b0 = __ldcs(p + TPB);
                const float a1 = __ldcs(p + o1);
                const float b1 = __ldcs(p + o1 + TPB);
                const float a2 = __ldcs(p + o2);
                const float b2 = __ldcs(p + o2 + TPB);
                const float a3 = __ldcs(p + o3);
                const float b3 = __ldcs(p + o3 + TPB);
                acc0 = fmaf(xi0, a0, acc0);  acc1 = fmaf(xi0, b0, acc1);
                acc0 = fmaf(xi1, a1, acc0);  acc1 = fmaf(xi1, b1, acc1);
                acc0 = fmaf(xi2, a2, acc0);  acc1 = fmaf(xi2, b2, acc1);
                acc0 = fmaf(xi3, a3, acc0);  acc1 = fmaf(xi3, b3, acc1);
                p += 4 * n - 14 - 4 * i;
            }
        } else {
            // ---- diagonal path: 4-row unroll, unguarded loads (addresses
            //      always in-bounds), FMAs predicated on j > i ----
            int i = i0;
            #pragma unroll 1
            for (; i + 4 <= iend; i += 4) {
                const int o1 = n - 2 - i;
                const int o2 = 2 * n - 5 - 2 * i;
                const int o3 = 3 * n - 9 - 3 * i;
                const float xi0 = __ldg(x + i);
                const float xi1 = __ldg(x + i + 1);
                const float xi2 = __ldg(x + i + 2);
                const float xi3 = __ldg(x + i + 3);
                const float a0 = __ldcs(p);
                const float b0 = __ldcs(p + TPB);
                const float a1 = __ldcs(p + o1);
                const float b1 = __ldcs(p + o1 + TPB);
                const float a2 = __ldcs(p + o2);
                const float b2 = __ldcs(p + o2 + TPB);
                const float a3 = __ldcs(p + o3);
                const float b3 = __ldcs(p + o3 + TPB);
                if (j_a > i)     acc0 = fmaf(xi0, a0, acc0);
                if (j_b > i)     acc1 = fmaf(xi0, b0, acc1);
                if (j_a > i + 1) acc0 = fmaf(xi1, a1, acc0);
                if (j_b > i + 1) acc1 = fmaf(xi1, b1, acc1);
                if (j_a > i + 2) acc0 = fmaf(xi2, a2, acc0);
                if (j_b > i + 2) acc1 = fmaf(xi2, b2, acc1);
                if (j_a > i + 3) acc0 = fmaf(xi3, a3, acc0);
                if (j_b > i + 3) acc1 = fmaf(xi3, b3, acc1);
                p += 4 * n - 14 - 4 * i;
            }
            // remainder rows (iend - i < 4)
            for (; i < iend; ++i) {
                const float xi = __ldg(x + i);
                const float ca = __ldcs(p);
                const float cb = __ldcs(p + TPB);
                if (j_a > i) acc0 = fmaf(xi, ca, acc0);
                if (j_b > i) acc1 = fmaf(xi, cb, acc1);
                p += n - 2 - i;
            }
        }

        sum += acc0 * __ldg(x + j_a) + acc1 * __ldg(x + j_b);
    }

    // block reduction: warp shuffle -> smem -> warp 0 -> one atomic per block
    __shared__ float wsum[TPB / 32];
    float w = warp_sum(sum);
    if ((t & 31) == 0) wsum[t >> 5] = w;
    __syncthreads();
    if (t < 32) {
        float v = (t < TPB / 32) ? wsum[t] : 0.0f;
        v = warp_sum(v);
        if (t == 0) atomicAdd(out, v);
    }
}

extern "C" void kernel_launch(void* const* d_in, const int* in_sizes, int n_in,
                              void* d_out, int out_size) {
    const float* x = (const float*)d_in[0];
    const float* c = (const float*)d_in[1];
    float* out = (float*)d_out;
    const int n = in_sizes[0];   // 8192

    zero_out_kernel<<<1, 32>>>(out);
    ham_kernel<<<NBLOCKS, TPB>>>(x, c, out, n);
}

// round 17
// speedup vs baseline: 1.1184x; 1.1184x over previous
#include <cuda_runtime.h>

#define TPB     256
#define NBLOCKS 1088     // 4352 tiles / 1088 = exactly 4 tiles per block
#define W       512      // column-strip width (= 2 * TPB)
#define H       16       // rows per tile

// ---------------------------------------------------------------------------
// out = sum_j x[j] * ( c1[j] + sum_{i<j} x[i] * c2[base(i) + (j-i-1)] )
// c2 = c + n, base(i) = i*(2n-1-i)/2  (row-major packed upper triangle).
//
// R3 tile kernel (best basin: 28.26us, DRAM 61.8%) with:
//  (1) grid = 1088 -> exactly 4 tiles/block, no quantization tail
//  (2) analytic strip decode (1 fsqrt + <=1 fixup) instead of linear search
//  (3) diagonal tiles: 4-row unroll, unguarded in-bounds loads, predicated
//      FMAs -> clean-path MLP on the 11.8% diagonal tiles
// ---------------------------------------------------------------------------

__global__ void zero_out_kernel(float* out) {
    if (threadIdx.x == 0 && blockIdx.x == 0) out[0] = 0.0f;
}

__device__ __forceinline__ float warp_sum(float v) {
    #pragma unroll
    for (int o = 16; o > 0; o >>= 1) v += __shfl_down_sync(0xffffffffu, v, o);
    return v;
}

__global__ __launch_bounds__(TPB, 8)
void ham_kernel(const float* __restrict__ x,
                const float* __restrict__ c,
                float* __restrict__ out,
                int n) {
    const int t = threadIdx.x;
    const int G = gridDim.x;
    const float* c2 = c + n;

    const int nstrips = n / W;                                   // 16
    const int ntiles  = (W / H / 2) * nstrips * (nstrips + 1);   // 4352

    float sum = 0.0f;

    for (int f = blockIdx.x; f < ntiles; f += G) {
        // strip js = largest with 16*js*(js+1) <= f  (analytic + fixup)
        int js = (int)((__fsqrt_rn((float)f * 0.0625f + 0.25f) - 0.5f));
        while (16 * (js + 1) * (js + 2) <= f) ++js;
        while (16 * js * (js + 1) > f) --js;
        const int it = f - 16 * js * (js + 1);

        const int j0  = js * W;
        const int i0  = it * H;
        const int j_a = j0 + t;
        const int j_b = j0 + TPB + t;

        float acc0 = 0.0f, acc1 = 0.0f;
        if (it == 0) {                       // fold degree-1 terms in once
            acc0 = __ldg(c + j_a);
            acc1 = __ldg(c + j_b);
        }

        int iend = i0 + H;
        const int ilim = (js + 1) * W - 1;   // rows valid while i < ilim
        if (iend > ilim) iend = ilim;

        const int base = (i0 * (2 * n - 1 - i0)) >> 1;   // < 2^27, exact
        const float* p = c2 + base + (j_a - i0 - 1);

        if (i0 + H <= j0) {
            // ---- clean path: whole tile strictly above diagonal ----
            #pragma unroll 1
            for (int i = i0; i + 4 <= iend; i += 4) {
                const int o1 = n - 2 - i;
                const int o2 = 2 * n - 5 - 2 * i;
                const int o3 = 3 * n - 9 - 3 * i;
                const float xi0 = __ldg(x + i);
                const float xi1 = __ldg(x + i + 1);
                const float xi2 = __ldg(x + i + 2);
                const float xi3 = __ldg(x + i + 3);
                // 8 independent streaming loads in flight
                const float a0 = __ldcs(p);
                const float b0 = __ldcs(p + TPB);
                const float a1 = __ldcs(p + o1);
                const float b1 = __ldcs(p + o1 + TPB);
                const float a2 = __ldcs(p + o2);
                const float b2 = __ldcs(p + o2 + TPB);
                const float a3 = __ldcs(p + o3);
                const float b3 = __ldcs(p + o3 + TPB);
                acc0 = fmaf(xi0, a0, acc0);  acc1 = fmaf(xi0, b0, acc1);
                acc0 = fmaf(xi1, a1, acc0);  acc1 = fmaf(xi1, b1, acc1);
                acc0 = fmaf(xi2, a2, acc0);  acc1 = fmaf(xi2, b2, acc1);
                acc0 = fmaf(xi3, a3, acc0);  acc1 = fmaf(xi3, b3, acc1);
                p += 4 * n - 14 - 4 * i;
            }
        } else {
            // ---- diagonal path: 4-row unroll, unguarded in-bounds loads,
            //      FMAs predicated on j > i ----
            int i = i0;
            #pragma unroll 1
            for (; i + 4 <= iend; i += 4) {
                const int o1 = n - 2 - i;
                const int o2 = 2 * n - 5 - 2 * i;
                const int o3 = 3 * n - 9 - 3 * i;
                const float xi0 = __ldg(x + i);
                const float xi1 = __ldg(x + i + 1);
                const float xi2 = __ldg(x + i + 2);
                const float xi3 = __ldg(x + i + 3);
                const float a0 = __ldcs(p);
                const float b0 = __ldcs(p + TPB);
                const float a1 = __ldcs(p + o1);
                const float b1 = __ldcs(p + o1 + TPB);
                const float a2 = __ldcs(p + o2);
                const float b2 = __ldcs(p + o2 + TPB);
                const float a3 = __ldcs(p + o3);
                const float b3 = __ldcs(p + o3 + TPB);
                if (j_a > i)     acc0 = fmaf(xi0, a0, acc0);
                if (j_b > i)     acc1 = fmaf(xi0, b0, acc1);
                if (j_a > i + 1) acc0 = fmaf(xi1, a1, acc0);
                if (j_b > i + 1) acc1 = fmaf(xi1, b1, acc1);
                if (j_a > i + 2) acc0 = fmaf(xi2, a2, acc0);
                if (j_b > i + 2) acc1 = fmaf(xi2, b2, acc1);
                if (j_a > i + 3) acc0 = fmaf(xi3, a3, acc0);
                if (j_b > i + 3) acc1 = fmaf(xi3, b3, acc1);
                p += 4 * n - 14 - 4 * i;
            }
            for (; i < iend; ++i) {
                const float xi = __ldg(x + i);
                const float ca = __ldcs(p);
                const float cb = __ldcs(p + TPB);
                if (j_a > i) acc0 = fmaf(xi, ca, acc0);
                if (j_b > i) acc1 = fmaf(xi, cb, acc1);
                p += n - 2 - i;
            }
        }

        sum += acc0 * __ldg(x + j_a) + acc1 * __ldg(x + j_b);
    }

    // block reduction: warp shuffle -> smem -> warp 0 -> one atomic per block
    __shared__ float wsum[TPB / 32];
    float w = warp_sum(sum);
    if ((t & 31) == 0) wsum[t >> 5] = w;
    __syncthreads();
    if (t < 32) {
        float v = (t < TPB / 32) ? wsum[t] : 0.0f;
        v = warp_sum(v);
        if (t == 0) atomicAdd(out, v);
    }
}

extern "C" void kernel_launch(void* const* d_in, const int* in_sizes, int n_in,
                              void* d_out, int out_size) {
    const float* x = (const float*)d_in[0];
    const float* c = (const float*)d_in[1];
    float* out = (float*)d_out;
    const int n = in_sizes[0];   // 8192

    zero_out_kernel<<<1, 32>>>(out);
    ham_kernel<<<NBLOCKS, TPB>>>(x, c, out, n);
}